// round 1
// baseline (speedup 1.0000x reference)
#include <cuda_runtime.h>
#include <cuda_bf16.h>
#include <mma.h>

using namespace nvcuda;

// Problem constants (fixed shapes from reference)
#define B_SZ 8192
#define N_SZ 8192
#define D_SZ 1024
#define EPS_F 1e-6f
__device__ __constant__ float c_dummy; // (none needed; keep file simple)

constexpr float INV_T = 1.0f / 0.92f;

// ---------------- scratch (device globals; no allocations allowed) ----------
__device__ __nv_bfloat16 g_qhat[(size_t)B_SZ * D_SZ]; // 16 MB
__device__ __nv_bfloat16 g_nhat[(size_t)N_SZ * D_SZ]; // 16 MB
__device__ float g_s1[B_SZ];   // exp(pos_sim / T)
__device__ float g_S2[B_SZ];   // sum over negatives of exp(neg_sim / T)

// ---------------------------------------------------------------------------
// Kernel 1: per-row (b): norms of q,p ; pos_sim ; write qhat=q/||q|| as bf16;
//           zero S2[b]. One block per row, 256 threads, D=1024 -> float4 each.
// ---------------------------------------------------------------------------
__global__ __launch_bounds__(256) void prep_qp_kernel(const float* __restrict__ q,
                                                      const float* __restrict__ p) {
    const int b = blockIdx.x;
    const int t = threadIdx.x;
    const float4* q4 = (const float4*)(q + (size_t)b * D_SZ);
    const float4* p4 = (const float4*)(p + (size_t)b * D_SZ);

    float4 a = q4[t];
    float4 c = p4[t];
    float qq = a.x * a.x + a.y * a.y + a.z * a.z + a.w * a.w;
    float pp = c.x * c.x + c.y * c.y + c.z * c.z + c.w * c.w;
    float qp = a.x * c.x + a.y * c.y + a.z * c.z + a.w * c.w;

    // warp reduce
    #pragma unroll
    for (int off = 16; off > 0; off >>= 1) {
        qq += __shfl_xor_sync(0xffffffff, qq, off);
        pp += __shfl_xor_sync(0xffffffff, pp, off);
        qp += __shfl_xor_sync(0xffffffff, qp, off);
    }
    __shared__ float sq[8], sp[8], sqp[8], s_rq;
    const int wid = t >> 5, lane = t & 31;
    if (lane == 0) { sq[wid] = qq; sp[wid] = pp; sqp[wid] = qp; }
    __syncthreads();
    if (t == 0) {
        float tq = 0.f, tp = 0.f, tqp = 0.f;
        #pragma unroll
        for (int i = 0; i < 8; i++) { tq += sq[i]; tp += sp[i]; tqp += sqp[i]; }
        float qn = sqrtf(tq), pn = sqrtf(tp);
        float pos = tqp / fmaxf(qn * pn, EPS_F);
        g_s1[b] = __expf(pos * INV_T);
        g_S2[b] = 0.0f;
        s_rq = (qn > 0.f) ? (1.0f / qn) : 0.0f;
    }
    __syncthreads();
    const float rq = s_rq;
    __nv_bfloat16* out = g_qhat + (size_t)b * D_SZ + t * 4;
    out[0] = __float2bfloat16(a.x * rq);
    out[1] = __float2bfloat16(a.y * rq);
    out[2] = __float2bfloat16(a.z * rq);
    out[3] = __float2bfloat16(a.w * rq);
}

// ---------------------------------------------------------------------------
// Kernel 2: per-row (n): nhat = n/||n|| as bf16.
// ---------------------------------------------------------------------------
__global__ __launch_bounds__(256) void prep_n_kernel(const float* __restrict__ nkeys) {
    const int nrow = blockIdx.x;
    const int t = threadIdx.x;
    const float4* n4 = (const float4*)(nkeys + (size_t)nrow * D_SZ);
    float4 a = n4[t];
    float nn = a.x * a.x + a.y * a.y + a.z * a.z + a.w * a.w;
    #pragma unroll
    for (int off = 16; off > 0; off >>= 1) nn += __shfl_xor_sync(0xffffffff, nn, off);
    __shared__ float sn[8], s_rn;
    const int wid = t >> 5, lane = t & 31;
    if (lane == 0) sn[wid] = nn;
    __syncthreads();
    if (t == 0) {
        float tn = 0.f;
        #pragma unroll
        for (int i = 0; i < 8; i++) tn += sn[i];
        float norm = sqrtf(tn);
        s_rn = (norm > 0.f) ? (1.0f / norm) : 0.0f;
    }
    __syncthreads();
    const float rn = s_rn;
    __nv_bfloat16* out = g_nhat + (size_t)nrow * D_SZ + t * 4;
    out[0] = __float2bfloat16(a.x * rn);
    out[1] = __float2bfloat16(a.y * rn);
    out[2] = __float2bfloat16(a.z * rn);
    out[3] = __float2bfloat16(a.w * rn);
}

// ---------------------------------------------------------------------------
// Kernel 3: fused GEMM + exp + row-sum.
//   C[b,n] = qhat[b,:] . nhat[n,:]   (both unit vectors, bf16, fp32 accum)
//   S2[b] += sum_n exp(C[b,n] / T)
// Tiling: block = 128x128 output tile, 8 warps in 4x2 grid, each warp 32x64
// via 2x4 wmma 16x16x16 bf16 fragments. K chunk = 32 (2 wmma k-steps).
// Epilogue: per-warp smem scratch (16x20 fp32), exp via MUFU, rowsum via
// shuffle, atomicAdd into g_S2.
// ---------------------------------------------------------------------------
#define KP 40   // smem K pitch (elements) for A/B tiles: 80B rows, 16B-aligned
#define CP 20   // scratch pitch (floats)

__global__ __launch_bounds__(256) void gemm_exp_kernel() {
    __shared__ __nv_bfloat16 As[128 * KP];
    __shared__ __nv_bfloat16 Bs[128 * KP];
    __shared__ float cs[8][16 * CP];

    const int tid = threadIdx.x;
    const int wid = tid >> 5, lane = tid & 31;
    const int wm = wid >> 1;   // warp row 0..3  (32 rows each)
    const int wn = wid & 1;    // warp col 0..1  (64 cols each)
    const int m0 = blockIdx.y * 128;
    const int n0 = blockIdx.x * 128;

    wmma::fragment<wmma::accumulator, 16, 16, 16, float> acc[2][4];
    #pragma unroll
    for (int mf = 0; mf < 2; mf++)
        #pragma unroll
        for (int nf = 0; nf < 4; nf++)
            wmma::fill_fragment(acc[mf][nf], 0.0f);

    for (int kt = 0; kt < D_SZ / 32; kt++) {
        const int k0 = kt * 32;
        __syncthreads();
        // Load A (128x32) and B (128x32) tiles, 16B vectors.
        #pragma unroll
        for (int i = 0; i < 2; i++) {
            int idx = tid + i * 256;          // 0..511
            int row = idx >> 2;               // 0..127
            int seg = idx & 3;                // 0..3 (8 bf16 each)
            *(uint4*)&As[row * KP + seg * 8] =
                *(const uint4*)&g_qhat[(size_t)(m0 + row) * D_SZ + k0 + seg * 8];
            *(uint4*)&Bs[row * KP + seg * 8] =
                *(const uint4*)&g_nhat[(size_t)(n0 + row) * D_SZ + k0 + seg * 8];
        }
        __syncthreads();

        #pragma unroll
        for (int kk = 0; kk < 2; kk++) {
            wmma::fragment<wmma::matrix_a, 16, 16, 16, __nv_bfloat16, wmma::row_major> af[2];
            #pragma unroll
            for (int mf = 0; mf < 2; mf++)
                wmma::load_matrix_sync(af[mf], &As[(wm * 32 + mf * 16) * KP + kk * 16], KP);
            #pragma unroll
            for (int nf = 0; nf < 4; nf++) {
                wmma::fragment<wmma::matrix_b, 16, 16, 16, __nv_bfloat16, wmma::col_major> bf;
                wmma::load_matrix_sync(bf, &Bs[(wn * 64 + nf * 16) * KP + kk * 16], KP);
                #pragma unroll
                for (int mf = 0; mf < 2; mf++)
                    wmma::mma_sync(acc[mf][nf], af[mf], bf, acc[mf][nf]);
            }
        }
    }

    // Epilogue: exp + row sums. Each warp owns rows [wm*32 + mf*16 .. +16).
    #pragma unroll
    for (int mf = 0; mf < 2; mf++) {
        float partial = 0.0f;
        #pragma unroll
        for (int nf = 0; nf < 4; nf++) {
            wmma::store_matrix_sync(&cs[wid][0], acc[mf][nf], CP, wmma::mem_row_major);
            __syncwarp();
            const int r = lane & 15, h = lane >> 4;
            const float* p = &cs[wid][r * CP + h * 8];
            #pragma unroll
            for (int c = 0; c < 8; c++) partial += __expf(p[c] * INV_T);
            __syncwarp();
        }
        partial += __shfl_xor_sync(0xffffffff, partial, 16);
        if (lane < 16) {
            int grow = m0 + wm * 32 + mf * 16 + lane;
            atomicAdd(&g_S2[grow], partial);
        }
    }
}

// ---------------------------------------------------------------------------
// Kernel 4: loss = mean_b( -log(s1 / (s1 + S2/N)) ). One block.
// ---------------------------------------------------------------------------
__global__ __launch_bounds__(256) void finalize_kernel(float* __restrict__ out) {
    const int t = threadIdx.x;
    double acc = 0.0;
    const float invN = 1.0f / (float)N_SZ;
    for (int b = t; b < B_SZ; b += 256) {
        float s1 = g_s1[b];
        float s2 = g_S2[b] * invN;
        acc += (double)(-logf(s1 / (s1 + s2)));
    }
    __shared__ double sd[256];
    sd[t] = acc;
    __syncthreads();
    #pragma unroll
    for (int stride = 128; stride > 0; stride >>= 1) {
        if (t < stride) sd[t] += sd[t + stride];
        __syncthreads();
    }
    if (t == 0) out[0] = (float)(sd[0] / (double)B_SZ);
}

// ---------------------------------------------------------------------------
extern "C" void kernel_launch(void* const* d_in, const int* in_sizes, int n_in,
                              void* d_out, int out_size) {
    const float* q  = (const float*)d_in[0];   // [B,1,D]
    const float* p  = (const float*)d_in[1];   // [B,1,D]
    const float* nk = (const float*)d_in[2];   // [N,1,D]
    float* out = (float*)d_out;

    prep_qp_kernel<<<B_SZ, 256>>>(q, p);
    prep_n_kernel<<<N_SZ, 256>>>(nk);
    gemm_exp_kernel<<<dim3(N_SZ / 128, B_SZ / 128), 256>>>();
    finalize_kernel<<<1, 256>>>(out);
}

// round 3
// speedup vs baseline: 1.6649x; 1.6649x over previous
#include <cuda_runtime.h>
#include <cuda_bf16.h>
#include <mma.h>
#include <cstdint>

using namespace nvcuda;

#define B_SZ 8192
#define N_SZ 8192
#define D_SZ 1024
#define EPS_F 1e-6f
constexpr float INV_T = 1.0f / 0.92f;

// ---------------- scratch (device globals; no allocations allowed) ----------
__device__ __nv_bfloat16 g_qhat[(size_t)B_SZ * D_SZ]; // 16 MB
__device__ __nv_bfloat16 g_nhat[(size_t)N_SZ * D_SZ]; // 16 MB
__device__ float g_s1[B_SZ];
__device__ float g_S2[B_SZ];
__device__ float g_loss;

// ---------------------------------------------------------------------------
#define CP_ASYNC16(dst, src) \
    asm volatile("cp.async.cg.shared.global [%0], [%1], 16;" :: "r"(dst), "l"(src) : "memory")
#define CP_COMMIT() asm volatile("cp.async.commit_group;" ::: "memory")
#define CP_WAIT1()  asm volatile("cp.async.wait_group 1;" ::: "memory")

__device__ __forceinline__ uint32_t smem_u32(const void* p) {
    uint32_t a;
    asm("{ .reg .u64 t; cvta.to.shared.u64 t, %1; cvt.u32.u64 %0, t; }"
        : "=r"(a) : "l"(p));
    return a;
}

// ---------------------------------------------------------------------------
// Kernel 1: prep q,p -> qhat (bf16), s1, zero S2/loss
// ---------------------------------------------------------------------------
__global__ __launch_bounds__(256) void prep_qp_kernel(const float* __restrict__ q,
                                                      const float* __restrict__ p) {
    const int b = blockIdx.x;
    const int t = threadIdx.x;
    const float4* q4 = (const float4*)(q + (size_t)b * D_SZ);
    const float4* p4 = (const float4*)(p + (size_t)b * D_SZ);

    float4 a = q4[t];
    float4 c = p4[t];
    float qq = a.x * a.x + a.y * a.y + a.z * a.z + a.w * a.w;
    float pp = c.x * c.x + c.y * c.y + c.z * c.z + c.w * c.w;
    float qp = a.x * c.x + a.y * c.y + a.z * c.z + a.w * c.w;

    #pragma unroll
    for (int off = 16; off > 0; off >>= 1) {
        qq += __shfl_xor_sync(0xffffffff, qq, off);
        pp += __shfl_xor_sync(0xffffffff, pp, off);
        qp += __shfl_xor_sync(0xffffffff, qp, off);
    }
    __shared__ float sq[8], sp[8], sqp[8], s_rq;
    const int wid = t >> 5, lane = t & 31;
    if (lane == 0) { sq[wid] = qq; sp[wid] = pp; sqp[wid] = qp; }
    __syncthreads();
    if (t == 0) {
        float tq = 0.f, tp = 0.f, tqp = 0.f;
        #pragma unroll
        for (int i = 0; i < 8; i++) { tq += sq[i]; tp += sp[i]; tqp += sqp[i]; }
        float qn = sqrtf(tq), pn = sqrtf(tp);
        float pos = tqp / fmaxf(qn * pn, EPS_F);
        g_s1[b] = __expf(pos * INV_T);
        g_S2[b] = 0.0f;
        if (b == 0) g_loss = 0.0f;
        s_rq = (qn > 0.f) ? (1.0f / qn) : 0.0f;
    }
    __syncthreads();
    const float rq = s_rq;
    __nv_bfloat16* out = g_qhat + (size_t)b * D_SZ + t * 4;
    out[0] = __float2bfloat16(a.x * rq);
    out[1] = __float2bfloat16(a.y * rq);
    out[2] = __float2bfloat16(a.z * rq);
    out[3] = __float2bfloat16(a.w * rq);
}

// ---------------------------------------------------------------------------
// Kernel 2: prep negatives -> nhat (bf16)
// ---------------------------------------------------------------------------
__global__ __launch_bounds__(256) void prep_n_kernel(const float* __restrict__ nkeys) {
    const int nrow = blockIdx.x;
    const int t = threadIdx.x;
    const float4* n4 = (const float4*)(nkeys + (size_t)nrow * D_SZ);
    float4 a = n4[t];
    float nn = a.x * a.x + a.y * a.y + a.z * a.z + a.w * a.w;
    #pragma unroll
    for (int off = 16; off > 0; off >>= 1) nn += __shfl_xor_sync(0xffffffff, nn, off);
    __shared__ float sn[8], s_rn;
    const int wid = t >> 5, lane = t & 31;
    if (lane == 0) sn[wid] = nn;
    __syncthreads();
    if (t == 0) {
        float tn = 0.f;
        #pragma unroll
        for (int i = 0; i < 8; i++) tn += sn[i];
        float norm = sqrtf(tn);
        s_rn = (norm > 0.f) ? (1.0f / norm) : 0.0f;
    }
    __syncthreads();
    const float rn = s_rn;
    __nv_bfloat16* out = g_nhat + (size_t)nrow * D_SZ + t * 4;
    out[0] = __float2bfloat16(a.x * rn);
    out[1] = __float2bfloat16(a.y * rn);
    out[2] = __float2bfloat16(a.z * rn);
    out[3] = __float2bfloat16(a.w * rn);
}

// ---------------------------------------------------------------------------
// Kernel 3: wmma GEMM (bf16->fp32) + fused exp/rowsum, 3-stage cp.async.
//   Block: 128(M) x 256(N), 512 threads (16 warps, 4x4), warp: 32x64.
//   K chunk 32, 3 stages. Smem row pitch 40 elems (80B) - conflict-free.
// ---------------------------------------------------------------------------
#define BM 128
#define BN 256
#define KC 32
#define CHUNKS (D_SZ / KC)        // 32
#define KP 40                     // smem row pitch in bf16 elems (80B)
#define A_ST (BM * KP)            // 5120 elems = 10240B
#define B_ST (BN * KP)            // 10240 elems = 20480B
#define STAGE_ELEMS (A_ST + B_ST) // 15360 elems = 30720B
#define SMEM_BYTES (3 * STAGE_ELEMS * 2)   // 92160
#define CP 20                     // epilogue scratch pitch (floats)

__global__ __launch_bounds__(512, 1) void gemm_exp_kernel() {
    extern __shared__ __nv_bfloat16 sm[];
    const int tid = threadIdx.x;
    const int wid = tid >> 5, lane = tid & 31;
    const int wm = wid >> 2;          // 0..3 -> 32-row strip
    const int wn = wid & 3;           // 0..3 -> 64-col strip
    const int m0 = blockIdx.y * BM;
    const int n0 = blockIdx.x * BN;

    // cp.async slots: A: 1 vec/thread (512 = 128 rows x 4 segs)
    //                 B: 2 vec/thread (1024 = 256 rows x 4 segs)
    const int a_row = tid >> 2, a_seg = tid & 3;
    const uint32_t a_off = (uint32_t)(a_row * KP + a_seg * 8) * 2;  // bytes
    const __nv_bfloat16* a_src = g_qhat + (size_t)(m0 + a_row) * D_SZ + a_seg * 8;

    uint32_t b_off[2];
    const __nv_bfloat16* b_src[2];
    #pragma unroll
    for (int i = 0; i < 2; i++) {
        int idx = tid + i * 512;
        int row = idx >> 2, seg = idx & 3;
        b_off[i] = (uint32_t)(A_ST + row * KP + seg * 8) * 2;
        b_src[i] = g_nhat + (size_t)(n0 + row) * D_SZ + seg * 8;
    }

    const uint32_t sbase = smem_u32(sm);

    wmma::fragment<wmma::accumulator, 16, 16, 16, float> acc[2][4];
    #pragma unroll
    for (int mf = 0; mf < 2; mf++)
        #pragma unroll
        for (int nf = 0; nf < 4; nf++)
            wmma::fill_fragment(acc[mf][nf], 0.0f);

    // Prologue: chunks 0,1
    #pragma unroll
    for (int s = 0; s < 2; s++) {
        uint32_t st = sbase + s * (STAGE_ELEMS * 2);
        int k0 = s * KC;
        CP_ASYNC16(st + a_off, a_src + k0);
        CP_ASYNC16(st + b_off[0], b_src[0] + k0);
        CP_ASYNC16(st + b_off[1], b_src[1] + k0);
        CP_COMMIT();
    }

    for (int kt = 0; kt < CHUNKS; kt++) {
        CP_WAIT1();
        __syncthreads();

        // Prefetch chunk kt+2 into slot (kt+2)%3 == (kt-1)%3 (freed last iter)
        int pf = kt + 2;
        if (pf < CHUNKS) {
            uint32_t st = sbase + (pf % 3) * (STAGE_ELEMS * 2);
            int k0 = pf * KC;
            CP_ASYNC16(st + a_off, a_src + k0);
            CP_ASYNC16(st + b_off[0], b_src[0] + k0);
            CP_ASYNC16(st + b_off[1], b_src[1] + k0);
        }
        CP_COMMIT();

        // Compute chunk kt from slot kt%3
        const __nv_bfloat16* As = sm + (kt % 3) * STAGE_ELEMS;
        const __nv_bfloat16* Bs = As + A_ST;
        #pragma unroll
        for (int kk = 0; kk < 2; kk++) {
            wmma::fragment<wmma::matrix_a, 16, 16, 16, __nv_bfloat16, wmma::row_major> af[2];
            #pragma unroll
            for (int mf = 0; mf < 2; mf++)
                wmma::load_matrix_sync(af[mf], As + (wm * 32 + mf * 16) * KP + kk * 16, KP);
            #pragma unroll
            for (int nf = 0; nf < 4; nf++) {
                wmma::fragment<wmma::matrix_b, 16, 16, 16, __nv_bfloat16, wmma::col_major> bf;
                wmma::load_matrix_sync(bf, Bs + (wn * 64 + nf * 16) * KP + kk * 16, KP);
                #pragma unroll
                for (int mf = 0; mf < 2; mf++)
                    wmma::mma_sync(acc[mf][nf], af[mf], bf, acc[mf][nf]);
            }
        }
    }

    // Epilogue: overlay scratch on pipeline smem (all loads/MMA done).
    __syncthreads();
    float* scratch = (float*)sm + wid * (16 * CP);
    #pragma unroll
    for (int mf = 0; mf < 2; mf++) {
        float partial = 0.0f;
        #pragma unroll
        for (int nf = 0; nf < 4; nf++) {
            wmma::store_matrix_sync(scratch, acc[mf][nf], CP, wmma::mem_row_major);
            __syncwarp();
            const int r = lane & 15, h = lane >> 4;
            const float* pr = scratch + r * CP + h * 8;
            #pragma unroll
            for (int c = 0; c < 8; c++) partial += __expf(pr[c] * INV_T);
            __syncwarp();
        }
        partial += __shfl_xor_sync(0xffffffff, partial, 16);
        if (lane < 16)
            atomicAdd(&g_S2[m0 + wm * 32 + mf * 16 + lane], partial);
    }
}

// ---------------------------------------------------------------------------
// Kernel 4: per-row loss terms -> block partials -> g_loss; then write out.
// ---------------------------------------------------------------------------
__global__ __launch_bounds__(256) void finalize_partial_kernel() {
    const int b = blockIdx.x * 256 + threadIdx.x;
    float s1 = g_s1[b];
    float s2 = g_S2[b] * (1.0f / (float)N_SZ);
    float v = -logf(s1 / (s1 + s2));

    __shared__ float sd[256];
    sd[threadIdx.x] = v;
    __syncthreads();
    #pragma unroll
    for (int stride = 128; stride > 0; stride >>= 1) {
        if (threadIdx.x < stride) sd[threadIdx.x] += sd[threadIdx.x + stride];
        __syncthreads();
    }
    if (threadIdx.x == 0) atomicAdd(&g_loss, sd[0]);
}

__global__ void finalize_write_kernel(float* __restrict__ out) {
    out[0] = g_loss * (1.0f / (float)B_SZ);
}

// ---------------------------------------------------------------------------
extern "C" void kernel_launch(void* const* d_in, const int* in_sizes, int n_in,
                              void* d_out, int out_size) {
    const float* q  = (const float*)d_in[0];
    const float* p  = (const float*)d_in[1];
    const float* nk = (const float*)d_in[2];
    float* out = (float*)d_out;

    cudaFuncSetAttribute(gemm_exp_kernel,
                         cudaFuncAttributeMaxDynamicSharedMemorySize, SMEM_BYTES);

    prep_qp_kernel<<<B_SZ, 256>>>(q, p);
    prep_n_kernel<<<N_SZ, 256>>>(nk);
    gemm_exp_kernel<<<dim3(N_SZ / BN, B_SZ / BM), 512, SMEM_BYTES>>>();
    finalize_partial_kernel<<<B_SZ / 256, 256>>>();
    finalize_write_kernel<<<1, 1>>>(out);
}

// round 4
// speedup vs baseline: 1.9174x; 1.1516x over previous
#include <cuda_runtime.h>
#include <cuda_bf16.h>
#include <mma.h>
#include <cstdint>

using namespace nvcuda;

#define B_SZ 8192
#define N_SZ 8192
#define D_SZ 1024
#define EPS_F 1e-6f
constexpr float INV_T = 1.0f / 0.92f;

// ---------------- scratch (device globals; no allocations allowed) ----------
__device__ __nv_bfloat16 g_qhat[(size_t)B_SZ * D_SZ]; // 16 MB
__device__ __nv_bfloat16 g_nhat[(size_t)N_SZ * D_SZ]; // 16 MB
__device__ float g_s1[B_SZ];
__device__ float g_S2[B_SZ];
__device__ float g_loss;

// ---------------------------------------------------------------------------
#define CP_ASYNC16(dst, src) \
    asm volatile("cp.async.cg.shared.global [%0], [%1], 16;" :: "r"(dst), "l"(src) : "memory")
#define CP_COMMIT() asm volatile("cp.async.commit_group;" ::: "memory")
#define CP_WAIT1()  asm volatile("cp.async.wait_group 1;" ::: "memory")

__device__ __forceinline__ uint32_t smem_u32(const void* p) {
    uint32_t a;
    asm("{ .reg .u64 t; cvta.to.shared.u64 t, %1; cvt.u32.u64 %0, t; }"
        : "=r"(a) : "l"(p));
    return a;
}

// ---------------------------------------------------------------------------
// Kernel 1: prep q,p -> qhat (bf16), s1, zero S2/loss
// ---------------------------------------------------------------------------
__global__ __launch_bounds__(256) void prep_qp_kernel(const float* __restrict__ q,
                                                      const float* __restrict__ p) {
    const int b = blockIdx.x;
    const int t = threadIdx.x;
    const float4* q4 = (const float4*)(q + (size_t)b * D_SZ);
    const float4* p4 = (const float4*)(p + (size_t)b * D_SZ);

    float4 a = q4[t];
    float4 c = p4[t];
    float qq = a.x * a.x + a.y * a.y + a.z * a.z + a.w * a.w;
    float pp = c.x * c.x + c.y * c.y + c.z * c.z + c.w * c.w;
    float qp = a.x * c.x + a.y * c.y + a.z * c.z + a.w * c.w;

    #pragma unroll
    for (int off = 16; off > 0; off >>= 1) {
        qq += __shfl_xor_sync(0xffffffff, qq, off);
        pp += __shfl_xor_sync(0xffffffff, pp, off);
        qp += __shfl_xor_sync(0xffffffff, qp, off);
    }
    __shared__ float sq[8], sp[8], sqp[8], s_rq;
    const int wid = t >> 5, lane = t & 31;
    if (lane == 0) { sq[wid] = qq; sp[wid] = pp; sqp[wid] = qp; }
    __syncthreads();
    if (t == 0) {
        float tq = 0.f, tp = 0.f, tqp = 0.f;
        #pragma unroll
        for (int i = 0; i < 8; i++) { tq += sq[i]; tp += sp[i]; tqp += sqp[i]; }
        float qn = sqrtf(tq), pn = sqrtf(tp);
        float pos = tqp / fmaxf(qn * pn, EPS_F);
        g_s1[b] = __expf(pos * INV_T);
        g_S2[b] = 0.0f;
        if (b == 0) g_loss = 0.0f;
        s_rq = (qn > 0.f) ? (1.0f / qn) : 0.0f;
    }
    __syncthreads();
    const float rq = s_rq;
    __nv_bfloat16* out = g_qhat + (size_t)b * D_SZ + t * 4;
    out[0] = __float2bfloat16(a.x * rq);
    out[1] = __float2bfloat16(a.y * rq);
    out[2] = __float2bfloat16(a.z * rq);
    out[3] = __float2bfloat16(a.w * rq);
}

// ---------------------------------------------------------------------------
// Kernel 2: prep negatives -> nhat (bf16)
// ---------------------------------------------------------------------------
__global__ __launch_bounds__(256) void prep_n_kernel(const float* __restrict__ nkeys) {
    const int nrow = blockIdx.x;
    const int t = threadIdx.x;
    const float4* n4 = (const float4*)(nkeys + (size_t)nrow * D_SZ);
    float4 a = n4[t];
    float nn = a.x * a.x + a.y * a.y + a.z * a.z + a.w * a.w;
    #pragma unroll
    for (int off = 16; off > 0; off >>= 1) nn += __shfl_xor_sync(0xffffffff, nn, off);
    __shared__ float sn[8], s_rn;
    const int wid = t >> 5, lane = t & 31;
    if (lane == 0) sn[wid] = nn;
    __syncthreads();
    if (t == 0) {
        float tn = 0.f;
        #pragma unroll
        for (int i = 0; i < 8; i++) tn += sn[i];
        float norm = sqrtf(tn);
        s_rn = (norm > 0.f) ? (1.0f / norm) : 0.0f;
    }
    __syncthreads();
    const float rn = s_rn;
    __nv_bfloat16* out = g_nhat + (size_t)nrow * D_SZ + t * 4;
    out[0] = __float2bfloat16(a.x * rn);
    out[1] = __float2bfloat16(a.y * rn);
    out[2] = __float2bfloat16(a.z * rn);
    out[3] = __float2bfloat16(a.w * rn);
}

// ---------------------------------------------------------------------------
// Kernel 3: wmma GEMM (bf16->fp32) + fused exp/rowsum, 3-stage cp.async.
//   Block: 128(M) x 256(N), 256 threads (8 warps, 2x4), warp tile: 64x64.
//   K chunk 64, 3 stages, pitch 72 elems (144B rows, conflict-free LDSM).
// ---------------------------------------------------------------------------
#define BM 128
#define BN 256
#define KC 64
#define CHUNKS (D_SZ / KC)        // 16
#define KP 72                     // smem row pitch (bf16 elems), 144B
#define A_ST (BM * KP)            // 9216 elems
#define B_ST (BN * KP)            // 18432 elems
#define STAGE_ELEMS (A_ST + B_ST) // 27648 elems = 55296 B
#define SMEM_BYTES (3 * STAGE_ELEMS * 2)   // 165888
#define CP 20

__global__ __launch_bounds__(256, 1) void gemm_exp_kernel() {
    extern __shared__ __nv_bfloat16 sm[];
    const int tid = threadIdx.x;
    const int wid = tid >> 5, lane = tid & 31;
    const int wm = wid >> 2;          // 0..1 -> 64-row strip
    const int wn = wid & 3;           // 0..3 -> 64-col strip
    const int m0 = blockIdx.y * BM;
    const int n0 = blockIdx.x * BN;

    // cp.async slots per chunk: A rows have 8 16B-segs (64 bf16).
    //   A: 128*8 = 1024 vecs -> 4/thread.  B: 256*8 = 2048 -> 8/thread.
    uint32_t a_off[4], b_off[8];
    const __nv_bfloat16* a_src[4];
    const __nv_bfloat16* b_src[8];
    #pragma unroll
    for (int i = 0; i < 4; i++) {
        int idx = tid + i * 256;
        int row = idx >> 3, seg = idx & 7;
        a_off[i] = (uint32_t)(row * KP + seg * 8) * 2;
        a_src[i] = g_qhat + (size_t)(m0 + row) * D_SZ + seg * 8;
    }
    #pragma unroll
    for (int i = 0; i < 8; i++) {
        int idx = tid + i * 256;
        int row = idx >> 3, seg = idx & 7;
        b_off[i] = (uint32_t)(A_ST + row * KP + seg * 8) * 2;
        b_src[i] = g_nhat + (size_t)(n0 + row) * D_SZ + seg * 8;
    }

    const uint32_t sbase = smem_u32(sm);

    wmma::fragment<wmma::accumulator, 16, 16, 16, float> acc[4][4];
    #pragma unroll
    for (int mf = 0; mf < 4; mf++)
        #pragma unroll
        for (int nf = 0; nf < 4; nf++)
            wmma::fill_fragment(acc[mf][nf], 0.0f);

    // Prologue: chunks 0,1
    #pragma unroll
    for (int s = 0; s < 2; s++) {
        uint32_t st = sbase + s * (STAGE_ELEMS * 2);
        int k0 = s * KC;
        #pragma unroll
        for (int i = 0; i < 4; i++) CP_ASYNC16(st + a_off[i], a_src[i] + k0);
        #pragma unroll
        for (int i = 0; i < 8; i++) CP_ASYNC16(st + b_off[i], b_src[i] + k0);
        CP_COMMIT();
    }

    for (int kt = 0; kt < CHUNKS; kt++) {
        CP_WAIT1();
        __syncthreads();

        int pf = kt + 2;
        if (pf < CHUNKS) {
            uint32_t st = sbase + (pf % 3) * (STAGE_ELEMS * 2);
            int k0 = pf * KC;
            #pragma unroll
            for (int i = 0; i < 4; i++) CP_ASYNC16(st + a_off[i], a_src[i] + k0);
            #pragma unroll
            for (int i = 0; i < 8; i++) CP_ASYNC16(st + b_off[i], b_src[i] + k0);
        }
        CP_COMMIT();

        const __nv_bfloat16* As = sm + (kt % 3) * STAGE_ELEMS;
        const __nv_bfloat16* Bs = As + A_ST;
        #pragma unroll
        for (int kk = 0; kk < 4; kk++) {
            wmma::fragment<wmma::matrix_a, 16, 16, 16, __nv_bfloat16, wmma::row_major> af[4];
            #pragma unroll
            for (int mf = 0; mf < 4; mf++)
                wmma::load_matrix_sync(af[mf], As + (wm * 64 + mf * 16) * KP + kk * 16, KP);
            #pragma unroll
            for (int nf = 0; nf < 4; nf++) {
                wmma::fragment<wmma::matrix_b, 16, 16, 16, __nv_bfloat16, wmma::col_major> bf;
                wmma::load_matrix_sync(bf, Bs + (wn * 64 + nf * 16) * KP + kk * 16, KP);
                #pragma unroll
                for (int mf = 0; mf < 4; mf++)
                    wmma::mma_sync(acc[mf][nf], af[mf], bf, acc[mf][nf]);
            }
        }
    }

    // Epilogue: overlay scratch on pipeline smem (all loads/MMA done).
    __syncthreads();
    float* scratch = (float*)sm + wid * (16 * CP);
    #pragma unroll
    for (int mf = 0; mf < 4; mf++) {
        float partial = 0.0f;
        #pragma unroll
        for (int nf = 0; nf < 4; nf++) {
            wmma::store_matrix_sync(scratch, acc[mf][nf], CP, wmma::mem_row_major);
            __syncwarp();
            const int r = lane & 15, h = lane >> 4;
            const float* pr = scratch + r * CP + h * 8;
            #pragma unroll
            for (int c = 0; c < 8; c++) partial += __expf(pr[c] * INV_T);
            __syncwarp();
        }
        partial += __shfl_xor_sync(0xffffffff, partial, 16);
        if (lane < 16)
            atomicAdd(&g_S2[m0 + wm * 64 + mf * 16 + lane], partial);
    }
}

// ---------------------------------------------------------------------------
// Kernel 4: per-row loss terms -> block partials -> g_loss; then write out.
// ---------------------------------------------------------------------------
__global__ __launch_bounds__(256) void finalize_partial_kernel() {
    const int b = blockIdx.x * 256 + threadIdx.x;
    float s1 = g_s1[b];
    float s2 = g_S2[b] * (1.0f / (float)N_SZ);
    float v = -logf(s1 / (s1 + s2));

    __shared__ float sd[256];
    sd[threadIdx.x] = v;
    __syncthreads();
    #pragma unroll
    for (int stride = 128; stride > 0; stride >>= 1) {
        if (threadIdx.x < stride) sd[threadIdx.x] += sd[threadIdx.x + stride];
        __syncthreads();
    }
    if (threadIdx.x == 0) atomicAdd(&g_loss, sd[0]);
}

__global__ void finalize_write_kernel(float* __restrict__ out) {
    out[0] = g_loss * (1.0f / (float)B_SZ);
}

// ---------------------------------------------------------------------------
extern "C" void kernel_launch(void* const* d_in, const int* in_sizes, int n_in,
                              void* d_out, int out_size) {
    const float* q  = (const float*)d_in[0];
    const float* p  = (const float*)d_in[1];
    const float* nk = (const float*)d_in[2];
    float* out = (float*)d_out;

    cudaFuncSetAttribute(gemm_exp_kernel,
                         cudaFuncAttributeMaxDynamicSharedMemorySize, SMEM_BYTES);

    prep_qp_kernel<<<B_SZ, 256>>>(q, p);
    prep_n_kernel<<<N_SZ, 256>>>(nk);
    gemm_exp_kernel<<<dim3(N_SZ / BN, B_SZ / BM), 256, SMEM_BYTES>>>();
    finalize_partial_kernel<<<B_SZ / 256, 256>>>();
    finalize_write_kernel<<<1, 1>>>(out);
}